// round 8
// baseline (speedup 1.0000x reference)
#include <cuda_runtime.h>
#include <cuda_bf16.h>
#include <cstdint>

#define SEQL  256
#define BATCHN 64
#define EMBD  256
#define HID   512
#define OUTD  18
#define MROWS (SEQL*BATCHN)   // 16384

typedef unsigned long long u64;

// ---------------- packed f32x2 helpers ----------------
__device__ __forceinline__ u64 ffma2(u64 a, u64 b, u64 c) {
    u64 d; asm("fma.rn.f32x2 %0, %1, %2, %3;" : "=l"(d) : "l"(a), "l"(b), "l"(c));
    return d;
}
__device__ __forceinline__ u64 pack2(float lo, float hi) {
    u64 r; asm("mov.b64 %0, {%1, %2};" : "=l"(r) : "f"(lo), "f"(hi));
    return r;
}
__device__ __forceinline__ float2 unpk2(u64 v) {
    float lo, hi; asm("mov.b64 {%0, %1}, %2;" : "=f"(lo), "=f"(hi) : "l"(v));
    return make_float2(lo, hi);
}

// remote smem float4 store: same smem offset in CTA `rank` of the cluster
__device__ __forceinline__ void st_cluster_f4(uint32_t local_addr, uint32_t rank,
                                              float a, float b, float c, float d) {
    asm volatile(
        "{\n\t.reg .b32 ra;\n\t"
        "mapa.shared::cluster.u32 ra, %0, %1;\n\t"
        "st.shared::cluster.v4.f32 [ra], {%2, %3, %4, %5};\n\t}"
        :: "r"(local_addr), "r"(rank), "f"(a), "f"(b), "f"(c), "f"(d) : "memory");
}

// ---------------- scratch (static device arrays; no allocation) ----------------
__device__ float g_post_emb[MROWS * EMBD];            // 16 MB
__device__ float g_xp0[2 * SEQL * BATCHN * HID];      // 64 MB  [d][s][b][h]
__device__ float g_h0 [MROWS * 2 * HID];              // 64 MB  [s][b][2H]
__device__ float g_xp1[2 * SEQL * BATCHN * HID];      // 64 MB
__device__ float g_h1 [MROWS * 2 * HID];              // 64 MB

// =====================================================================
// fp32 SIMT GEMM, f32x2 FMA (unchanged — passing since round 5)
// =====================================================================
template<int GATHER, int SCATTER, int NBIAS, int BN>
__global__ void __launch_bounds__(256, 2)
gemm_k(const float* __restrict__ A, const float* __restrict__ Bw,
       const float* __restrict__ bias1, const float* __restrict__ bias2,
       float* __restrict__ C,
       const int* __restrict__ gidx, const float* __restrict__ gtab,
       int N, int K, int nOff, int Nfull)
{
    constexpr int BM = 128, BK = 16;
    constexpr int COLS = BN / 16;
    constexpr int BF4  = BN / 64;
    __shared__ float As[2][BK][BM];
    __shared__ float Bs[2][BK][BN];

    const int tid   = threadIdx.x;
    const int mBase = blockIdx.y * BM;
    const int nBase = blockIdx.x * BN;
    const int tx = tid & 15;
    const int ty = tid >> 4;

    const int ar0 = tid >> 2;
    const int ak4 = (tid & 3) * 4;
    const int br  = (BN == 128) ? (tid >> 1) : (tid >> 2);
    const int bko = (BN == 128) ? ((tid & 1) * 8) : ((tid & 3) * 4);

    const int row0 = mBase + ar0;
    const int row1 = row0 + 64;
    const float* arp0;
    const float* arp1;
    if (GATHER) {
        arp0 = gtab + (size_t)gidx[row0] * K;
        arp1 = gtab + (size_t)gidx[row1] * K;
    } else {
        arp0 = A + (size_t)row0 * K;
        arp1 = A + (size_t)row1 * K;
    }
    const int brow = nBase + br;
    const float* brp = (brow < N) ? (Bw + (size_t)brow * K) : nullptr;

    const int KT = K / BK;

    float4 a0r, a1r, b0r[BF4];

    a0r = *reinterpret_cast<const float4*>(arp0 + ak4);
    a1r = *reinterpret_cast<const float4*>(arp1 + ak4);
    #pragma unroll
    for (int f = 0; f < BF4; f++)
        b0r[f] = brp ? *reinterpret_cast<const float4*>(brp + bko + 4 * f)
                     : make_float4(0.f, 0.f, 0.f, 0.f);
    {
        As[0][ak4+0][ar0]    = a0r.x; As[0][ak4+1][ar0]    = a0r.y;
        As[0][ak4+2][ar0]    = a0r.z; As[0][ak4+3][ar0]    = a0r.w;
        As[0][ak4+0][ar0+64] = a1r.x; As[0][ak4+1][ar0+64] = a1r.y;
        As[0][ak4+2][ar0+64] = a1r.z; As[0][ak4+3][ar0+64] = a1r.w;
        #pragma unroll
        for (int f = 0; f < BF4; f++) {
            Bs[0][bko+4*f+0][br] = b0r[f].x; Bs[0][bko+4*f+1][br] = b0r[f].y;
            Bs[0][bko+4*f+2][br] = b0r[f].z; Bs[0][bko+4*f+3][br] = b0r[f].w;
        }
    }
    __syncthreads();

    u64 acc2[4][COLS];
    #pragma unroll
    for (int i = 0; i < 4; i++)
        #pragma unroll
        for (int j = 0; j < COLS; j++) acc2[i][j] = 0ull;

    #pragma unroll 1
    for (int kt = 0; kt < KT; kt++) {
        const int buf = kt & 1;
        if (kt + 1 < KT) {
            const int ka = (kt + 1) * BK;
            a0r = *reinterpret_cast<const float4*>(arp0 + ka + ak4);
            a1r = *reinterpret_cast<const float4*>(arp1 + ka + ak4);
            #pragma unroll
            for (int f = 0; f < BF4; f++)
                b0r[f] = brp ? *reinterpret_cast<const float4*>(brp + ka + bko + 4 * f)
                             : make_float4(0.f, 0.f, 0.f, 0.f);
        }
        #pragma unroll
        for (int k = 0; k < BK; k++) {
            ulonglong2 aA = *reinterpret_cast<const ulonglong2*>(&As[buf][k][ty * 8]);
            ulonglong2 aB = *reinterpret_cast<const ulonglong2*>(&As[buf][k][ty * 8 + 4]);
            u64 a2[4] = {aA.x, aA.y, aB.x, aB.y};
            u64 b2[COLS];
            #pragma unroll
            for (int f = 0; f < BF4; f++) {
                float4 bf = *reinterpret_cast<const float4*>(&Bs[buf][k][tx * COLS + 4 * f]);
                b2[4*f+0] = pack2(bf.x, bf.x); b2[4*f+1] = pack2(bf.y, bf.y);
                b2[4*f+2] = pack2(bf.z, bf.z); b2[4*f+3] = pack2(bf.w, bf.w);
            }
            #pragma unroll
            for (int i = 0; i < 4; i++)
                #pragma unroll
                for (int j = 0; j < COLS; j++)
                    acc2[i][j] = ffma2(a2[i], b2[j], acc2[i][j]);
        }
        if (kt + 1 < KT) {
            const int nb = (kt + 1) & 1;
            As[nb][ak4+0][ar0]    = a0r.x; As[nb][ak4+1][ar0]    = a0r.y;
            As[nb][ak4+2][ar0]    = a0r.z; As[nb][ak4+3][ar0]    = a0r.w;
            As[nb][ak4+0][ar0+64] = a1r.x; As[nb][ak4+1][ar0+64] = a1r.y;
            As[nb][ak4+2][ar0+64] = a1r.z; As[nb][ak4+3][ar0+64] = a1r.w;
            #pragma unroll
            for (int f = 0; f < BF4; f++) {
                Bs[nb][bko+4*f+0][br] = b0r[f].x; Bs[nb][bko+4*f+1][br] = b0r[f].y;
                Bs[nb][bko+4*f+2][br] = b0r[f].z; Bs[nb][bko+4*f+3][br] = b0r[f].w;
            }
            __syncthreads();
        }
    }

    #pragma unroll
    for (int i2 = 0; i2 < 4; i2++) {
        #pragma unroll
        for (int j = 0; j < COLS; j++) {
            const int n = tx * COLS + j;
            if (nBase + n >= N) continue;
            const int nglob = nBase + n + nOff;
            float2 v2 = unpk2(acc2[i2][j]);
            float bsum = 0.f;
            if (NBIAS >= 1) bsum += bias1[nglob];
            if (NBIAS >= 2) bsum += bias2[nglob];
            #pragma unroll
            for (int half = 0; half < 2; half++) {
                const int m = mBase + ty * 8 + i2 * 2 + half;
                float v = (half ? v2.y : v2.x) + bsum;
                if (SCATTER) {
                    const int s = m >> 6, b = m & 63, d = nglob >> 9, h = nglob & 511;
                    C[(size_t)d * (SEQL * BATCHN * HID) +
                      (size_t)s * (BATCHN * HID) + b * HID + h] = v;
                } else {
                    C[(size_t)m * Nfull + nglob] = v;
                }
            }
        }
    }
}

// =====================================================================
// Recurrence v3: 16 clusters x 8 CTAs, 512 threads/CTA.
// cluster = (dir d, batch-octet g); CTA rank r owns 64 outputs.
// thread (c = t>>6, oo = t&63): W row r*64+oo, k-chunk [64c,64c+64) in
// 32 u64 regs; accumulates over 8 batches from LOCAL smem h (broadcast
// LDS). Results pushed to all 8 peers' smem via mapa+st.shared::cluster
// (DSMEM) — no L2 round trip. Sync = cluster barrier (release/acquire
// orders DSMEM stores). Double-buffered h; part reduce in smem.
// Dynamic smem: h[2][8][512] (32KB) + part[8][64][9] (18KB) = 50KB.
// =====================================================================
#define RNN_SMEM (2*8*512*4 + 8*64*9*4)

__global__ void __cluster_dims__(8, 1, 1) __launch_bounds__(512, 1)
rnn_k(const float* __restrict__ xp,      // [2][SEQL][BATCHN][HID]
      const float* __restrict__ whh,     // [2][HID][HID]
      float* __restrict__ hout)          // [SEQL][BATCHN][2*HID]
{
    extern __shared__ float sm[];        // h: sm[0..8192), part: sm+8192
    const int r   = blockIdx.x & 7;
    const int cid = blockIdx.x >> 3;
    const int d   = cid & 1;
    const int g   = cid >> 1;
    const int t   = threadIdx.x;
    const int c   = t >> 6;              // k-chunk 0..7
    const int oo  = t & 63;
    const int ck  = c * 64;

    // --- W row slice (64 floats = 32 packed pairs) ---
    u64 Wp[32];
    {
        const float* wr = whh + (size_t)(d * HID + r * 64 + oo) * HID + ck;
        #pragma unroll
        for (int i = 0; i < 16; i++) {
            ulonglong2 v = *reinterpret_cast<const ulonglong2*>(wr + 4 * i);
            Wp[2 * i] = v.x; Wp[2 * i + 1] = v.y;
        }
    }

    // --- zero h buffer 0 (local copy; every CTA zeroes its own) ---
    reinterpret_cast<float4*>(sm)[t]       = make_float4(0.f, 0.f, 0.f, 0.f);
    reinterpret_cast<float4*>(sm)[t + 512] = make_float4(0.f, 0.f, 0.f, 0.f);
    __syncthreads();
    asm volatile("barrier.cluster.arrive.aligned;" ::: "memory");
    asm volatile("barrier.cluster.wait.aligned;"   ::: "memory");

    // reduce/push mapping: thread -> output (ol = t>>3, batch bb = t&7)
    const int ol   = t >> 3;             // 0..63
    const int bb   = t & 7;
    const int og   = t >> 5;             // warp id = ol>>2 (4-output group)
    const int lane = t & 31;
    const int gb   = g * 8 + bb;
    const int orF  = r * 64 + ol;

    float* partp = sm + 8192;

    float xv;
    {
        const int s0 = d ? (SEQL - 1) : 0;
        xv = xp[((size_t)(d * SEQL + s0) * BATCHN + gb) * HID + orF];
    }

    // local smem byte-address of my push target h[nb][lane][r*64+og*4]
    uint32_t sm_base;
    asm("{ .reg .u64 tt; cvta.to.shared.u64 tt, %1; cvt.u32.u64 %0, tt; }"
        : "=r"(sm_base) : "l"((void*)sm));
    const uint32_t push_off0 = sm_base + (uint32_t)((0 * 4096 + lane * 512 + r * 64 + og * 4) * 4);
    const uint32_t push_off1 = sm_base + (uint32_t)((1 * 4096 + lane * 512 + r * 64 + og * 4) * 4);

    #pragma unroll 1
    for (int step = 0; step < SEQL; step++) {
        const int s = d ? (SEQL - 1 - step) : step;
        const float* hb = sm + (step & 1) * 4096;

        // --- partial dot products: local broadcast LDS, 256 FFMA2 ---
        u64 acc[8];
        #pragma unroll
        for (int b = 0; b < 8; b++) acc[b] = 0ull;
        #pragma unroll
        for (int i = 0; i < 16; i++) {
            #pragma unroll
            for (int b = 0; b < 8; b++) {
                ulonglong2 hv = *reinterpret_cast<const ulonglong2*>(hb + b * 512 + ck + 4 * i);
                acc[b] = ffma2(Wp[2 * i],     hv.x, acc[b]);
                acc[b] = ffma2(Wp[2 * i + 1], hv.y, acc[b]);
            }
        }
        #pragma unroll
        for (int b = 0; b < 8; b++) {
            float2 f = unpk2(acc[b]);
            partp[(c * 64 + oo) * 9 + b] = f.x + f.y;
        }
        __syncthreads();

        // --- reduce 8 chunks; one output per thread ---
        float v = xv;
        #pragma unroll
        for (int cc = 0; cc < 8; cc++)
            v += partp[(cc * 64 + ol) * 9 + bb];
        v = fmaxf(v, 0.f);

        // gather 4 consecutive outputs (same batch) to owner lanes 0..7
        const float v0 = __shfl_sync(0xffffffffu, v, bb);
        const float v1 = __shfl_sync(0xffffffffu, v, 8 + bb);
        const float v2 = __shfl_sync(0xffffffffu, v, 16 + bb);
        const float v3 = __shfl_sync(0xffffffffu, v, 24 + bb);

        if (lane < 8) {
            const uint32_t po = ((step & 1) ? push_off0 : push_off1);
            #pragma unroll
            for (int p = 0; p < 8; p++)
                st_cluster_f4(po, (uint32_t)p, v0, v1, v2, v3);
            // hout write (off critical path)
            float4* ho = reinterpret_cast<float4*>(
                hout + ((size_t)s * BATCHN + g * 8 + lane) * (2 * HID) + d * HID + r * 64 + og * 4);
            *ho = make_float4(v0, v1, v2, v3);
        }

        asm volatile("barrier.cluster.arrive.aligned;" ::: "memory");
        // hidden: next-step xp prefetch
        if (step + 1 < SEQL) {
            const int sn = d ? (SEQL - 2 - step) : (step + 1);
            xv = xp[((size_t)(d * SEQL + sn) * BATCHN + gb) * HID + orF];
        }
        asm volatile("barrier.cluster.wait.aligned;" ::: "memory");
    }
}

// =====================================================================
extern "C" void kernel_launch(void* const* d_in, const int* in_sizes, int n_in,
                              void* d_out, int out_size)
{
    const int*   text   = (const int*)  d_in[0];
    const float* emb    = (const float*)d_in[1];
    const float* emfc_w = (const float*)d_in[2];
    const float* emfc_b = (const float*)d_in[3];
    const float* w_ih0  = (const float*)d_in[4];
    const float* w_hh0  = (const float*)d_in[5];
    const float* b_ih0  = (const float*)d_in[6];
    const float* b_hh0  = (const float*)d_in[7];
    const float* w_ih1  = (const float*)d_in[8];
    const float* w_hh1  = (const float*)d_in[9];
    const float* b_ih1  = (const float*)d_in[10];
    const float* b_hh1  = (const float*)d_in[11];
    const float* fc_w   = (const float*)d_in[12];
    const float* fc_b   = (const float*)d_in[13];
    float* out = (float*)d_out;

    float *p_pe, *p_xp0, *p_h0, *p_xp1, *p_h1;
    cudaGetSymbolAddress((void**)&p_pe,  g_post_emb);
    cudaGetSymbolAddress((void**)&p_xp0, g_xp0);
    cudaGetSymbolAddress((void**)&p_h0,  g_h0);
    cudaGetSymbolAddress((void**)&p_xp1, g_xp1);
    cudaGetSymbolAddress((void**)&p_h1,  g_h1);

    static int smem_set = 0;
    if (!smem_set) {
        cudaFuncSetAttribute(rnn_k, cudaFuncAttributeMaxDynamicSharedMemorySize, RNN_SMEM);
        smem_set = 1;
    }

    dim3 blk(256);

    // 0) post_emb = gather(emb_table, text) @ emfc_w^T + emfc_b        [16384,256]
    gemm_k<1,0,1,128><<<dim3(EMBD/128, MROWS/128), blk>>>(
        nullptr, emfc_w, emfc_b, nullptr, p_pe, text, emb, EMBD, EMBD, 0, EMBD);

    // 1-2) xp0 split by direction (keeps rnn_k at launch index 3 for ncu)
    gemm_k<0,1,2,128><<<dim3(512/128, MROWS/128), blk>>>(
        p_pe, w_ih0, b_ih0, b_hh0, p_xp0, nullptr, nullptr, 512, EMBD, 0, 0);
    gemm_k<0,1,2,128><<<dim3(512/128, MROWS/128), blk>>>(
        p_pe, w_ih0 + (size_t)512 * EMBD, b_ih0, b_hh0, p_xp0,
        nullptr, nullptr, 512, EMBD, 512, 0);

    // 3) layer-0 bidirectional recurrence -> h0 [s][b][1024]
    rnn_k<<<128, 512, RNN_SMEM>>>(p_xp0, w_hh0, p_h0);

    // 4) xp1 = h0 @ w_ih1^T + (b_ih1+b_hh1)                            N=1024,K=1024
    gemm_k<0,1,2,128><<<dim3(1024/128, MROWS/128), blk>>>(
        p_h0, w_ih1, b_ih1, b_hh1, p_xp1, nullptr, nullptr, 1024, 1024, 0, 0);

    // 5) layer-1 recurrence -> h1
    rnn_k<<<128, 512, RNN_SMEM>>>(p_xp1, w_hh1, p_h1);

    // 6) out = h1 @ fc_w^T + fc_b                                      N=18,K=1024
    gemm_k<0,0,1,64><<<dim3(1, MROWS/128), blk>>>(
        p_h1, fc_w, fc_b, nullptr, out, nullptr, nullptr, OUTD, 1024, 0, OUTD);
}